// round 2
// baseline (speedup 1.0000x reference)
#include <cuda_runtime.h>
#include <cuda_bf16.h>

#define IN_F   4096
#define OUT_F  4096
#define NTOK   16384
#define BW     8
#define KW     17          // 2*BW+1
#define NO     4           // outputs per thread
#define WARPS  8           // warps per block
#define GY     512         // token groups (grid.y)
#define WIN4   36          // float4 chunks per warp window (144 floats)
#define SBUF4  40          // padded chunks per buffer

// warp covers 32*NO = 128 consecutive outputs; block covers 1024; grid.x = 4.
__global__ __launch_bounds__(256, 2) void band_linear_kernel(
    const float* __restrict__ x,
    const float* __restrict__ w,
    const float* __restrict__ bias,
    float* __restrict__ out)
{
    __shared__ float4 sm[WARPS][2][SBUF4];

    const int warp = threadIdx.x >> 5;
    const int lane = threadIdx.x & 31;
    const int wbase  = (blockIdx.x * WARPS + warp) * (32 * NO); // warp's first output
    const int o_base = wbase + lane * NO;
    const int g0     = wbase - BW - (NO - BW);  // = wbase - 16? no: window start
    // window start for this warp: wbase - 8 (covers outputs wbase..wbase+127, taps +-8)
    const int win0 = wbase - BW;                 // multiple of 4 minus 8 -> mult of 4
    (void)g0;

    // ---- load 4x17 band weights + bias into registers (once per block) ----
    float wr[NO][KW];
    float br[NO];
#pragma unroll
    for (int oo = 0; oo < NO; ++oo) {
        const int o = o_base + oo;
        br[oo] = bias[o];
#pragma unroll
        for (int k = 0; k < KW; ++k) {
            const int i = o - BW + k;
            wr[oo][k] = (i >= 0 && i < IN_F) ? w[(long)o * IN_F + i] : 0.0f;
        }
    }

    // ---- staging chunk assignment (coalesced) ----
    const int  c0    = lane;            // chunk index 0..31
    const bool extra = (lane < WIN4 - 32);   // lanes 0..3 also load chunks 32..35
    const int  c1    = 32 + lane;

    int s0 = win0 + 4 * c0;
    s0 = s0 < 0 ? 0 : (s0 > IN_F - 4 ? IN_F - 4 : s0);
    int s1 = win0 + 4 * c1;
    s1 = s1 < 0 ? 0 : (s1 > IN_F - 4 ? IN_F - 4 : s1);
    // clamped chunks land at smem positions whose weights are zero -> harmless.

    int n = blockIdx.y;

    // ---- prologue: stage token n into buffer 0 ----
    {
        const float* __restrict__ xrow = x + (long)n * IN_F;
        float4 p0 = *reinterpret_cast<const float4*>(xrow + s0);
        sm[warp][0][c0] = p0;
        if (extra) {
            float4 p1 = *reinterpret_cast<const float4*>(xrow + s1);
            sm[warp][0][c1] = p1;
        }
    }
    __syncwarp();

    int buf = 0;
    for (; n < NTOK; n += GY) {
        const int nn = n + GY;
        const bool more = nn < NTOK;

        // ---- prefetch next token's chunks into registers ----
        float4 q0, q1;
        if (more) {
            const float* __restrict__ xnext = x + (long)nn * IN_F;
            q0 = *reinterpret_cast<const float4*>(xnext + s0);
            if (extra) q1 = *reinterpret_cast<const float4*>(xnext + s1);
        }

        // ---- compute current token from smem (conflict-free LDS.128) ----
        const float* sw = reinterpret_cast<const float*>(sm[warp][buf]);
        float xr[NO + 2 * BW];  // 20
#pragma unroll
        for (int c = 0; c < 5; ++c) {
            const float4 v = *reinterpret_cast<const float4*>(sw + lane * NO + 4 * c);
            xr[4 * c + 0] = v.x;
            xr[4 * c + 1] = v.y;
            xr[4 * c + 2] = v.z;
            xr[4 * c + 3] = v.w;
        }

        float acc[NO];
#pragma unroll
        for (int oo = 0; oo < NO; ++oo) {
            float a = br[oo];
#pragma unroll
            for (int k = 0; k < KW; ++k)
                a = fmaf(wr[oo][k], xr[oo + k], a);
            acc[oo] = a;
        }

        float4 o4;
        o4.x = acc[0]; o4.y = acc[1]; o4.z = acc[2]; o4.w = acc[3];
        *reinterpret_cast<float4*>(out + (long)n * OUT_F + o_base) = o4;

        // ---- stage prefetched token into the other buffer ----
        if (more) {
            sm[warp][buf ^ 1][c0] = q0;
            if (extra) sm[warp][buf ^ 1][c1] = q1;
        }
        __syncwarp();
        buf ^= 1;
    }
}

extern "C" void kernel_launch(void* const* d_in, const int* in_sizes, int n_in,
                              void* d_out, int out_size)
{
    const float* x    = (const float*)d_in[0];   // [NTOK, IN_F]
    const float* w    = (const float*)d_in[1];   // [OUT_F, IN_F]
    const float* bias = (const float*)d_in[2];   // [OUT_F]
    float* out = (float*)d_out;

    dim3 grid(OUT_F / (WARPS * 32 * NO), GY);    // (4, 512)
    dim3 block(WARPS * 32);                      // 256
    band_linear_kernel<<<grid, block>>>(x, w, bias, out);
}

// round 3
// speedup vs baseline: 1.4375x; 1.4375x over previous
#include <cuda_runtime.h>
#include <cuda_bf16.h>
#include <cstdint>

#define IN_F   4096
#define OUT_F  4096
#define NTOK   16384
#define BW     8
#define KW     17          // 2*BW+1
#define NO     4           // outputs per thread
#define WARPS  8           // warps per block
#define GY     512         // token groups (grid.y)
#define WIN4   36          // float4 chunks per warp window (144 floats)
#define SBUF4  40          // padded chunks per buffer
#define NBUF   5           // smem buffers per warp
#define PDIST  3           // prefetch distance (tokens ahead)

__device__ __forceinline__ void cp16(uint32_t dst_smem, const float* src) {
    asm volatile("cp.async.cg.shared.global [%0], [%1], 16;\n"
                 :: "r"(dst_smem), "l"(src) : "memory");
}
__device__ __forceinline__ void cp_commit() {
    asm volatile("cp.async.commit_group;\n" ::: "memory");
}
__device__ __forceinline__ void cp_wait3() {
    asm volatile("cp.async.wait_group %0;\n" :: "n"(PDIST) : "memory");
}

// warp covers 32*NO = 128 consecutive outputs; block covers 1024; grid.x = 4.
__global__ __launch_bounds__(256, 2) void band_linear_kernel(
    const float* __restrict__ x,
    const float* __restrict__ w,
    const float* __restrict__ bias,
    float* __restrict__ out)
{
    __shared__ float4 sm[WARPS][NBUF][SBUF4];

    const int warp = threadIdx.x >> 5;
    const int lane = threadIdx.x & 31;
    const int wbase  = (blockIdx.x * WARPS + warp) * (32 * NO);
    const int o_base = wbase + lane * NO;
    const int win0   = wbase - BW;              // multiple of 4 (mod 4 == 0 after -8)

    // ---- band weights + bias into registers (once) ----
    float wr[NO][KW];
    float br[NO];
#pragma unroll
    for (int oo = 0; oo < NO; ++oo) {
        const int o = o_base + oo;
        br[oo] = bias[o];
#pragma unroll
        for (int k = 0; k < KW; ++k) {
            const int i = o - BW + k;
            wr[oo][k] = (i >= 0 && i < IN_F) ? w[(long)o * IN_F + i] : 0.0f;
        }
    }

    // ---- staging chunk assignment (coalesced, 36 chunks over 32 lanes) ----
    const int  c0    = lane;
    const bool extra = (lane < WIN4 - 32);
    const int  c1    = 32 + lane;

    int s0 = win0 + 4 * c0;
    s0 = s0 < 0 ? 0 : (s0 > IN_F - 4 ? IN_F - 4 : s0);
    int s1 = win0 + 4 * c1;
    s1 = s1 < 0 ? 0 : (s1 > IN_F - 4 ? IN_F - 4 : s1);
    // clamped chunks pair only with zero weights -> harmless.

    const uint32_t wsm = (uint32_t)__cvta_generic_to_shared(&sm[warp][0][0]);
    const uint32_t off0 = (uint32_t)(c0 * 16);
    const uint32_t off1 = (uint32_t)(c1 * 16);

    const int n0 = blockIdx.y;

    // ---- prologue: stage tokens n0, n0+GY, n0+2GY into buffers 0..2 ----
#pragma unroll
    for (int p = 0; p < PDIST; ++p) {
        const int tn = n0 + p * GY;
        if (tn < NTOK) {
            const float* xrow = x + (long)tn * IN_F;
            const uint32_t b = wsm + (uint32_t)(p * SBUF4 * 16);
            cp16(b + off0, xrow + s0);
            if (extra) cp16(b + off1, xrow + s1);
        }
        cp_commit();
    }

    int buf = 0;      // buffer holding current token
    int pbuf = PDIST; // buffer to fill with token n + PDIST*GY
    for (int n = n0; n < NTOK; n += GY) {
        // ---- stage token n + PDIST*GY (depth-3 prefetch) ----
        const int pn = n + PDIST * GY;
        if (pn < NTOK) {
            const float* xrow = x + (long)pn * IN_F;
            const uint32_t b = wsm + (uint32_t)(pbuf * SBUF4 * 16);
            cp16(b + off0, xrow + s0);
            if (extra) cp16(b + off1, xrow + s1);
        }
        cp_commit();

        // ---- wait until token n's buffer is complete, make it warp-visible ----
        cp_wait3();
        __syncwarp();

        // ---- compute token n from smem (conflict-free LDS.128) ----
        const float* swp = reinterpret_cast<const float*>(&sm[warp][buf][0]);
        float xr[NO + 2 * BW];  // 20
#pragma unroll
        for (int c = 0; c < 5; ++c) {
            const float4 v = *reinterpret_cast<const float4*>(swp + lane * NO + 4 * c);
            xr[4 * c + 0] = v.x;
            xr[4 * c + 1] = v.y;
            xr[4 * c + 2] = v.z;
            xr[4 * c + 3] = v.w;
        }

        float acc[NO];
#pragma unroll
        for (int oo = 0; oo < NO; ++oo) {
            float a = br[oo];
#pragma unroll
            for (int k = 0; k < KW; ++k)
                a = fmaf(wr[oo][k], xr[oo + k], a);
            acc[oo] = a;
        }

        float4 o4;
        o4.x = acc[0]; o4.y = acc[1]; o4.z = acc[2]; o4.w = acc[3];
        *reinterpret_cast<float4*>(out + (long)n * OUT_F + o_base) = o4;

        buf  = (buf  + 1 == NBUF) ? 0 : buf  + 1;
        pbuf = (pbuf + 1 == NBUF) ? 0 : pbuf + 1;
        // NBUF=5 > PDIST+1: next iteration's write target was last read two
        // iterations ago; this iteration's syncwarp orders reads before writes.
    }
}

extern "C" void kernel_launch(void* const* d_in, const int* in_sizes, int n_in,
                              void* d_out, int out_size)
{
    const float* x    = (const float*)d_in[0];   // [NTOK, IN_F]
    const float* w    = (const float*)d_in[1];   // [OUT_F, IN_F]
    const float* bias = (const float*)d_in[2];   // [OUT_F]
    float* out = (float*)d_out;

    dim3 grid(OUT_F / (WARPS * 32 * NO), GY);    // (4, 512)
    dim3 block(WARPS * 32);                      // 256
    band_linear_kernel<<<grid, block>>>(x, w, bias, out);
}

// round 4
// speedup vs baseline: 1.4391x; 1.0011x over previous
#include <cuda_runtime.h>
#include <cuda_bf16.h>
#include <cstdint>

#define IN_F   4096
#define OUT_F  4096
#define NTOK   16384
#define BW     8
#define KW     17           // 2*BW+1
#define NO     8            // outputs per thread
#define WARPS  4            // warps per block (128 threads)
#define GY     512          // token groups (grid.y)
#define WIN_F  (32*NO + 2*BW)   // 272 floats per warp window
#define WIN4   (WIN_F/4)        // 68 chunks
#define SBUF4  76               // padded chunks per buffer (272 floats + pads -> 304 floats)
#define NBUF   5
#define PDIST  3

// padded smem float index: +4 floats of pad after every 32 floats
__device__ __forceinline__ int padidx(int j) { return j + ((j >> 5) << 2); }

__device__ __forceinline__ void cp16(uint32_t dst_smem, const float* src) {
    asm volatile("cp.async.cg.shared.global [%0], [%1], 16;\n"
                 :: "r"(dst_smem), "l"(src) : "memory");
}
__device__ __forceinline__ void cp_commit() {
    asm volatile("cp.async.commit_group;\n" ::: "memory");
}
__device__ __forceinline__ void cp_waitP() {
    asm volatile("cp.async.wait_group %0;\n" :: "n"(PDIST) : "memory");
}

// warp covers 32*NO = 256 consecutive outputs; block covers 1024; grid.x = 4.
__global__ __launch_bounds__(128, 2) void band_linear_kernel(
    const float* __restrict__ x,
    const float* __restrict__ w,
    const float* __restrict__ bias,
    float* __restrict__ out)
{
    __shared__ float4 sm[WARPS][NBUF][SBUF4];

    const int warp = threadIdx.x >> 5;
    const int lane = threadIdx.x & 31;
    const int wbase  = (blockIdx.x * WARPS + warp) * (32 * NO);
    const int o_base = wbase + lane * NO;
    const int win0   = wbase - BW;                 // multiple of 4

    // ---- 8x17 band weights + bias into registers (once per block) ----
    float wr[NO][KW];
    float br[NO];
#pragma unroll
    for (int oo = 0; oo < NO; ++oo) {
        const int o = o_base + oo;
        br[oo] = bias[o];
#pragma unroll
        for (int k = 0; k < KW; ++k) {
            const int i = o - BW + k;
            wr[oo][k] = (i >= 0 && i < IN_F) ? w[(long)o * IN_F + i] : 0.0f;
        }
    }

    // ---- staging chunk assignment: 68 chunks over 32 lanes (2 + 4 extra) ----
    const int  c0 = lane;
    const int  c1 = lane + 32;
    const bool extra = (lane < WIN4 - 64);   // lanes 0..3 take chunks 64..67
    const int  c2 = lane + 64;

    int s0 = win0 + 4 * c0;
    s0 = s0 < 0 ? 0 : (s0 > IN_F - 4 ? IN_F - 4 : s0);
    int s1 = win0 + 4 * c1;
    s1 = s1 < 0 ? 0 : (s1 > IN_F - 4 ? IN_F - 4 : s1);
    int s2 = win0 + 4 * c2;
    s2 = s2 < 0 ? 0 : (s2 > IN_F - 4 ? IN_F - 4 : s2);
    // clamped chunks pair only with zero weights -> harmless.

    const uint32_t wsm  = (uint32_t)__cvta_generic_to_shared(&sm[warp][0][0]);
    // padded destination chunk offsets (chunk c -> c + (c>>3) padded chunks)
    const uint32_t off0 = (uint32_t)((c0 + (c0 >> 3)) * 16);
    const uint32_t off1 = (uint32_t)((c1 + (c1 >> 3)) * 16);
    const uint32_t off2 = (uint32_t)((c2 + (c2 >> 3)) * 16);

    const int n0 = blockIdx.y;

    // ---- prologue: stage tokens n0 .. n0+2*GY into buffers 0..2 ----
#pragma unroll
    for (int p = 0; p < PDIST; ++p) {
        const int tn = n0 + p * GY;
        if (tn < NTOK) {
            const float* xrow = x + (long)tn * IN_F;
            const uint32_t b = wsm + (uint32_t)(p * SBUF4 * 16);
            cp16(b + off0, xrow + s0);
            cp16(b + off1, xrow + s1);
            if (extra) cp16(b + off2, xrow + s2);
        }
        cp_commit();
    }

    int buf = 0;
    int pbuf = PDIST;
    for (int n = n0; n < NTOK; n += GY) {
        // ---- stage token n + PDIST*GY ----
        const int pn = n + PDIST * GY;
        if (pn < NTOK) {
            const float* xrow = x + (long)pn * IN_F;
            const uint32_t b = wsm + (uint32_t)(pbuf * SBUF4 * 16);
            cp16(b + off0, xrow + s0);
            cp16(b + off1, xrow + s1);
            if (extra) cp16(b + off2, xrow + s2);
        }
        cp_commit();

        cp_waitP();
        __syncwarp();

        // ---- compute token n: 24-float window via 6 conflict-free LDS.128 ----
        const float* swp = reinterpret_cast<const float*>(&sm[warp][buf][0]);
        float xr[NO + 2 * BW];   // 24
#pragma unroll
        for (int c = 0; c < 6; ++c) {
            const int j0 = lane * NO + 4 * c;      // window float offset
            const float4 v = *reinterpret_cast<const float4*>(swp + padidx(j0));
            xr[4 * c + 0] = v.x;
            xr[4 * c + 1] = v.y;
            xr[4 * c + 2] = v.z;
            xr[4 * c + 3] = v.w;
        }

        float acc[NO];
#pragma unroll
        for (int oo = 0; oo < NO; ++oo) {
            float a = br[oo];
#pragma unroll
            for (int k = 0; k < KW; ++k)
                a = fmaf(wr[oo][k], xr[oo + k], a);
            acc[oo] = a;
        }

        float* orow = out + (long)n * OUT_F + o_base;
        float4 o4a, o4b;
        o4a.x = acc[0]; o4a.y = acc[1]; o4a.z = acc[2]; o4a.w = acc[3];
        o4b.x = acc[4]; o4b.y = acc[5]; o4b.z = acc[6]; o4b.w = acc[7];
        *reinterpret_cast<float4*>(orow)     = o4a;
        *reinterpret_cast<float4*>(orow + 4) = o4b;

        buf  = (buf  + 1 == NBUF) ? 0 : buf  + 1;
        pbuf = (pbuf + 1 == NBUF) ? 0 : pbuf + 1;
    }
}

extern "C" void kernel_launch(void* const* d_in, const int* in_sizes, int n_in,
                              void* d_out, int out_size)
{
    const float* x    = (const float*)d_in[0];   // [NTOK, IN_F]
    const float* w    = (const float*)d_in[1];   // [OUT_F, IN_F]
    const float* bias = (const float*)d_in[2];   // [OUT_F]
    float* out = (float*)d_out;

    dim3 grid(OUT_F / (WARPS * 32 * NO), GY);    // (4, 512)
    dim3 block(WARPS * 32);                      // 128
    band_linear_kernel<<<grid, block>>>(x, w, bias, out);
}